// round 5
// baseline (speedup 1.0000x reference)
#include <cuda_runtime.h>
#include <cstdint>

namespace {
constexpr int Bb = 16384, Ss = 5, Dd = 512, Hh = 8, HDd = 64;
constexpr int Mm = Bb * Ss;  // 81920
constexpr int BM = 128, BN = 256, BK = 16;
constexpr int KITERS = Dd / BK;           // 32
constexpr int SA_STRIDE = 20;             // conflict-free for a-frag LDS
constexpr int SB_STRIDE = 264;            // conflict-free for b-frag LDS
constexpr int A_STAGE = BM * SA_STRIDE;   // floats per stage
constexpr int B_STAGE = BK * SB_STRIDE;
constexpr int STAGES = 3;
constexpr int SMEM_BYTES = (STAGES * (A_STAGE + B_STAGE)) * 4;  // 81408 B
}

// Scratch (device globals: allocation-free rule)
__device__ float g_QKV[(size_t)Mm * 1536];  // [m][ q(512) | k(512) | v(512) ]
__device__ float g_O[(size_t)Mm * Dd];

__device__ __forceinline__ uint32_t to_tf32_u(float x) {
  float y;
  asm("cvt.rna.tf32.f32 %0, %1;" : "=f"(y) : "f"(x));
  return __float_as_uint(y);
}

__device__ __forceinline__ void mma_tf32(float c[4], uint32_t a0, uint32_t a1,
                                         uint32_t a2, uint32_t a3,
                                         uint32_t b0, uint32_t b1) {
  asm volatile(
      "mma.sync.aligned.m16n8k8.row.col.f32.tf32.tf32.f32 "
      "{%0,%1,%2,%3}, {%4,%5,%6,%7}, {%8,%9}, {%0,%1,%2,%3};"
      : "+f"(c[0]), "+f"(c[1]), "+f"(c[2]), "+f"(c[3])
      : "r"(a0), "r"(a1), "r"(a2), "r"(a3), "r"(b0), "r"(b1));
}

__device__ __forceinline__ void cp_async16(void* smem_ptr, const void* gptr) {
  uint32_t saddr = (uint32_t)__cvta_generic_to_shared(smem_ptr);
  asm volatile("cp.async.cg.shared.global [%0], [%1], 16;\n" ::"r"(saddr),
               "l"(gptr));
}
__device__ __forceinline__ void cp_commit() {
  asm volatile("cp.async.commit_group;\n" ::);
}
__device__ __forceinline__ void cp_wait1() {
  asm volatile("cp.async.wait_group 1;\n" ::);
}

// C[:, col0:col0+256] = A[M,512] @ W_sec + bias_sec  (sections of 512 cols)
__global__ __launch_bounds__(256) void gemm_tf32_kernel(
    const float* __restrict__ A, const float* __restrict__ W0,
    const float* __restrict__ W1, const float* __restrict__ W2,
    const float* __restrict__ bias0, const float* __restrict__ bias1,
    const float* __restrict__ bias2, float* __restrict__ Out, int ostride) {
  extern __shared__ float smem[];
  float* As = smem;                       // [STAGES][BM][SA_STRIDE]
  float* Bs = smem + STAGES * A_STAGE;    // [STAGES][BK][SB_STRIDE]

  const int tid = threadIdx.x;
  const int m0 = blockIdx.y * BM;
  const int col0 = blockIdx.x * BN;
  const int sec = col0 >> 9;
  const int n0 = col0 & 511;
  const float* W = (sec == 0) ? W0 : ((sec == 1) ? W1 : W2);
  const float* bias = (sec == 0) ? bias0 : ((sec == 1) ? bias1 : bias2);

  const int warp = tid >> 5, lane = tid & 31;
  const int g = lane >> 2, t = lane & 3;
  const int warp_m = (warp >> 2) * 64;  // 2 warps in m
  const int warp_n = (warp & 3) * 64;   // 4 warps in n

  float acc[4][8][4];
#pragma unroll
  for (int i = 0; i < 4; i++)
#pragma unroll
    for (int j = 0; j < 8; j++)
#pragma unroll
      for (int r = 0; r < 4; r++) acc[i][j][r] = 0.f;

  // cp.async mapping
  const int a_row0 = tid >> 2, a_q = (tid & 3) << 2;          // A: chunk tid, tid+256
  const int b_row = tid >> 6, b_q = (tid & 63) << 2;          // B: 4 chunks/thread

  auto issue_stage = [&](int it) {
    float* as = As + (it % STAGES) * A_STAGE;
    float* bs = Bs + (it % STAGES) * B_STAGE;
    int k0 = it * BK;
#pragma unroll
    for (int i = 0; i < 2; i++) {
      int row = a_row0 + i * 64;
      cp_async16(as + row * SA_STRIDE + a_q,
                 A + (size_t)(m0 + row) * Dd + k0 + a_q);
    }
#pragma unroll
    for (int i = 0; i < 4; i++) {
      int row = b_row + i * 4;
      cp_async16(bs + row * SB_STRIDE + b_q,
                 W + (size_t)(k0 + row) * Dd + n0 + b_q);
    }
    cp_commit();
  };

  issue_stage(0);
  issue_stage(1);

  for (int it = 0; it < KITERS; it++) {
    cp_wait1();
    __syncthreads();
    if (it + 2 < KITERS) issue_stage(it + 2);

    const float* as = As + (it % STAGES) * A_STAGE;
    const float* bs = Bs + (it % STAGES) * B_STAGE;
#pragma unroll
    for (int ks = 0; ks < BK; ks += 8) {
      uint32_t af[4][4], bf[8][2];
#pragma unroll
      for (int mi = 0; mi < 4; mi++) {
        const float* ap = as + (warp_m + mi * 16 + g) * SA_STRIDE + ks + t;
        af[mi][0] = to_tf32_u(ap[0]);
        af[mi][1] = to_tf32_u(ap[8 * SA_STRIDE]);
        af[mi][2] = to_tf32_u(ap[4]);
        af[mi][3] = to_tf32_u(ap[8 * SA_STRIDE + 4]);
      }
#pragma unroll
      for (int ni = 0; ni < 8; ni++) {
        const float* bp = bs + (ks + t) * SB_STRIDE + warp_n + ni * 8 + g;
        bf[ni][0] = to_tf32_u(bp[0]);
        bf[ni][1] = to_tf32_u(bp[4 * SB_STRIDE]);
      }
#pragma unroll
      for (int mi = 0; mi < 4; mi++)
#pragma unroll
        for (int ni = 0; ni < 8; ni++)
          mma_tf32(acc[mi][ni], af[mi][0], af[mi][1], af[mi][2], af[mi][3],
                   bf[ni][0], bf[ni][1]);
    }
    __syncthreads();
  }

  // epilogue: bias + store
#pragma unroll
  for (int mi = 0; mi < 4; mi++) {
    int r0 = m0 + warp_m + mi * 16 + g;
#pragma unroll
    for (int ni = 0; ni < 8; ni++) {
      int c = col0 + warp_n + ni * 8 + 2 * t;
      float b0v = bias[c & 511], b1v = bias[(c & 511) + 1];
      float2 v0 = make_float2(acc[mi][ni][0] + b0v, acc[mi][ni][1] + b1v);
      float2 v1 = make_float2(acc[mi][ni][2] + b0v, acc[mi][ni][3] + b1v);
      *reinterpret_cast<float2*>(Out + (size_t)r0 * ostride + c) = v0;
      *reinterpret_cast<float2*>(Out + (size_t)(r0 + 8) * ostride + c) = v1;
    }
  }
}

// One CTA per batch; warp h = head h. Contiguous 30KB float4 load of QKV.
__global__ __launch_bounds__(256) void attn_kernel(const float* __restrict__ pb) {
  __shared__ float sX[Ss * 1536];  // [s][ q | k | v ]
  __shared__ float sA[Hh][Ss][Ss];
  const int b = blockIdx.x;
  const int tid = threadIdx.x;
  const float* src = g_QKV + (size_t)b * (Ss * 1536);

  for (int i = tid; i < Ss * 1536 / 4; i += 256)
    reinterpret_cast<float4*>(sX)[i] = reinterpret_cast<const float4*>(src)[i];
  __syncthreads();

  const int h = tid >> 5, lane = tid & 31;
  const int c0 = h * HDd;

  if (lane < Ss * Ss) {
    int s = lane / Ss, tt = lane % Ss;
    float a = 0.f;
#pragma unroll
    for (int d = 0; d < HDd; d++)
      a += sX[s * 1536 + c0 + d] * sX[tt * 1536 + 512 + c0 + d];
    sA[h][s][tt] = a * 0.125f + pb[(h * Ss + s) * Ss + tt];
  }
  __syncwarp();

  if (lane < Ss) {
    float m = sA[h][lane][0];
#pragma unroll
    for (int tt = 1; tt < Ss; tt++) m = fmaxf(m, sA[h][lane][tt]);
    float e[Ss], sum = 0.f;
#pragma unroll
    for (int tt = 0; tt < Ss; tt++) {
      e[tt] = expf(sA[h][lane][tt] - m);
      sum += e[tt];
    }
    float inv = 1.0f / sum;
#pragma unroll
    for (int tt = 0; tt < Ss; tt++) sA[h][lane][tt] = e[tt] * inv;
  }
  __syncwarp();

  float* dst = g_O + (size_t)b * (Ss * Dd);
#pragma unroll
  for (int s = 0; s < Ss; s++) {
    float o0 = 0.f, o1 = 0.f;
#pragma unroll
    for (int tt = 0; tt < Ss; tt++) {
      float a = sA[h][s][tt];
      o0 += a * sX[tt * 1536 + 1024 + c0 + lane];
      o1 += a * sX[tt * 1536 + 1024 + c0 + lane + 32];
    }
    dst[s * Dd + c0 + lane] = o0;
    dst[s * Dd + c0 + lane + 32] = o1;
  }
}

extern "C" void kernel_launch(void* const* d_in, const int* in_sizes, int n_in,
                              void* d_out, int out_size) {
  (void)in_sizes; (void)n_in; (void)out_size;
  const float* x  = (const float*)d_in[0];
  const float* Wq = (const float*)d_in[1];
  const float* bq = (const float*)d_in[2];
  const float* Wk = (const float*)d_in[3];
  const float* bk = (const float*)d_in[4];
  const float* Wv = (const float*)d_in[5];
  const float* bv = (const float*)d_in[6];
  const float* Wo = (const float*)d_in[7];
  const float* bo = (const float*)d_in[8];
  const float* pb = (const float*)d_in[9];
  float* out = (float*)d_out;

  static bool attr_done = false;
  if (!attr_done) {
    cudaFuncSetAttribute(gemm_tf32_kernel,
                         cudaFuncAttributeMaxDynamicSharedMemorySize,
                         SMEM_BYTES);
    attr_done = true;
  }

  void *qkv = nullptr, *op = nullptr;
  cudaGetSymbolAddress(&qkv, g_QKV);
  cudaGetSymbolAddress(&op, g_O);

  // 1) fused QKV projection: [81920,512] x [512,1536] -> g_QKV [m][1536]
  dim3 grid1(1536 / BN, Mm / BM);
  gemm_tf32_kernel<<<grid1, 256, SMEM_BYTES>>>(
      x, Wq, Wk, Wv, bq, bk, bv, (float*)qkv, 1536);
  // 2) attention per batch
  attn_kernel<<<Bb, 256>>>(pb);
  // 3) output projection: [81920,512] x [512,512] -> d_out
  dim3 grid3(512 / BN, Mm / BM);
  gemm_tf32_kernel<<<grid3, 256, SMEM_BYTES>>>(
      (const float*)op, Wo, Wo, Wo, bo, bo, bo, out, 512);
}

// round 7
// speedup vs baseline: 1.0595x; 1.0595x over previous
#include <cuda_runtime.h>
#include <cstdint>

namespace {
constexpr int Bb = 16384, Ss = 5, Dd = 512, Hh = 8, HDd = 64;
constexpr int Mm = Bb * Ss;               // 81920
constexpr int BM = 128, BN = 256, BK = 16;
constexpr int KITERS = Dd / BK;           // 32
constexpr int SA_STRIDE = 20;             // conflict-free a-frag LDS
constexpr int SB_STRIDE = 264;            // conflict-free b-frag LDS
constexpr int A_STAGE = BM * SA_STRIDE;   // 2560 floats
constexpr int B_STAGE = BK * SB_STRIDE;   // 4224 floats
constexpr int STAGE_F = A_STAGE + B_STAGE;        // 6784 floats
constexpr int STAGES = 5;
constexpr int SMEM_BYTES = STAGES * STAGE_F * 4;  // 135680 B
}

// Scratch (device globals: allocation-free rule)
__device__ float g_X[(size_t)Mm * Dd];      // rna(x)
__device__ float g_QKV[(size_t)Mm * 1536];  // [m][ q | k | v ]
__device__ float g_O[(size_t)Mm * Dd];      // rna(attn out)
__device__ float g_Wr[4 * 512 * 512];       // rna(Wq|Wk|Wv|Wo), original [k][n] layout

__device__ __forceinline__ float to_tf32(float x) {
  float y;
  asm("cvt.rna.tf32.f32 %0, %1;" : "=f"(y) : "f"(x));
  return y;
}

__device__ __forceinline__ void mma_tf32(float c[4], uint32_t a0, uint32_t a1,
                                         uint32_t a2, uint32_t a3,
                                         uint32_t b0, uint32_t b1) {
  asm volatile(
      "mma.sync.aligned.m16n8k8.row.col.f32.tf32.tf32.f32 "
      "{%0,%1,%2,%3}, {%4,%5,%6,%7}, {%8,%9}, {%0,%1,%2,%3};"
      : "+f"(c[0]), "+f"(c[1]), "+f"(c[2]), "+f"(c[3])
      : "r"(a0), "r"(a1), "r"(a2), "r"(a3), "r"(b0), "r"(b1));
}

__device__ __forceinline__ void cp_async16(void* smem_ptr, const void* gptr) {
  uint32_t saddr = (uint32_t)__cvta_generic_to_shared(smem_ptr);
  asm volatile("cp.async.cg.shared.global [%0], [%1], 16;" ::"r"(saddr),
               "l"(gptr));
}
__device__ __forceinline__ void cp_commit() {
  asm volatile("cp.async.commit_group;" ::);
}

// Out[:, col0:col0+256] = A[M,512] @ W_sec[512,512] + bias_sec
// A and W are PRE-ROUNDED to tf32 values (no in-loop cvt).
__global__ __launch_bounds__(256, 1) void gemm_tf32_kernel(
    const float* __restrict__ A, const float* __restrict__ W0,
    const float* __restrict__ W1, const float* __restrict__ W2,
    const float* __restrict__ bias0, const float* __restrict__ bias1,
    const float* __restrict__ bias2, float* __restrict__ Out, int ostride) {
  extern __shared__ float smem[];

  const int tid = threadIdx.x;
  const int m0 = blockIdx.y * BM;
  const int col0 = blockIdx.x * BN;
  const int sec = col0 >> 9;
  const int n0 = col0 & 511;
  const float* W = (sec == 0) ? W0 : ((sec == 1) ? W1 : W2);
  const float* bias = (sec == 0) ? bias0 : ((sec == 1) ? bias1 : bias2);

  const int warp = tid >> 5, lane = tid & 31;
  const int g = lane >> 2, t = lane & 3;
  const int warp_m = (warp >> 2) * 64;  // 2 warps in m
  const int warp_n = (warp & 3) * 64;   // 4 warps in n

  float acc[4][8][4];
#pragma unroll
  for (int i = 0; i < 4; i++)
#pragma unroll
    for (int j = 0; j < 8; j++)
#pragma unroll
      for (int r = 0; r < 4; r++) acc[i][j][r] = 0.f;

  // cp.async mapping: A 512 chunks (2/thr), B 1024 chunks (4/thr)
  const int a_row0 = tid >> 2, a_q = (tid & 3) << 2;
  const int b_row0 = tid >> 6, b_q = (tid & 63) << 2;

  auto issue_stage = [&](int it) {
    float* as = smem + (it % STAGES) * STAGE_F;
    float* bs = as + A_STAGE;
    const int k0 = it * BK;
#pragma unroll
    for (int i = 0; i < 2; i++) {
      int row = a_row0 + i * 64;
      cp_async16(as + row * SA_STRIDE + a_q,
                 A + (size_t)(m0 + row) * Dd + k0 + a_q);
    }
#pragma unroll
    for (int i = 0; i < 4; i++) {
      int kk = b_row0 + i * 4;
      cp_async16(bs + kk * SB_STRIDE + b_q,
                 W + (size_t)(k0 + kk) * Dd + n0 + b_q);
    }
    cp_commit();
  };

  issue_stage(0);
  issue_stage(1);
  issue_stage(2);

  for (int it = 0; it < KITERS; it++) {
    if (it < KITERS - 2)
      asm volatile("cp.async.wait_group 2;" ::: "memory");
    else if (it == KITERS - 2)
      asm volatile("cp.async.wait_group 1;" ::: "memory");
    else
      asm volatile("cp.async.wait_group 0;" ::: "memory");

    // prefetch BEFORE the barrier: with 5 stages, buffer (it+3)%5 cannot
    // collide with compute(it-1)=(it+4)%5 or compute(it)=(it)%5.
    if (it + 3 < KITERS) issue_stage(it + 3);
    __syncthreads();

    const float* as = smem + (it % STAGES) * STAGE_F;
    const float* bs = as + A_STAGE;
#pragma unroll
    for (int ks = 0; ks < BK; ks += 8) {
      uint32_t af[4][4], bf[8][2];
#pragma unroll
      for (int mi = 0; mi < 4; mi++) {
        const float* ap = as + (warp_m + mi * 16 + g) * SA_STRIDE + ks + t;
        af[mi][0] = __float_as_uint(ap[0]);
        af[mi][1] = __float_as_uint(ap[8 * SA_STRIDE]);
        af[mi][2] = __float_as_uint(ap[4]);
        af[mi][3] = __float_as_uint(ap[8 * SA_STRIDE + 4]);
      }
#pragma unroll
      for (int ni = 0; ni < 8; ni++) {
        const float* bp = bs + (ks + t) * SB_STRIDE + warp_n + ni * 8 + g;
        bf[ni][0] = __float_as_uint(bp[0]);
        bf[ni][1] = __float_as_uint(bp[4 * SB_STRIDE]);
      }
#pragma unroll
      for (int mi = 0; mi < 4; mi++)
#pragma unroll
        for (int ni = 0; ni < 8; ni++)
          mma_tf32(acc[mi][ni], af[mi][0], af[mi][1], af[mi][2], af[mi][3],
                   bf[ni][0], bf[ni][1]);
    }
    __syncthreads();
  }

  // epilogue: bias + store (no smem use)
#pragma unroll
  for (int mi = 0; mi < 4; mi++) {
    int r0 = m0 + warp_m + mi * 16 + g;
#pragma unroll
    for (int ni = 0; ni < 8; ni++) {
      int c = col0 + warp_n + ni * 8 + 2 * t;
      float b0v = bias[c & 511], b1v = bias[(c & 511) + 1];
      float2 v0 = make_float2(acc[mi][ni][0] + b0v, acc[mi][ni][1] + b1v);
      float2 v1 = make_float2(acc[mi][ni][2] + b0v, acc[mi][ni][3] + b1v);
      *reinterpret_cast<float2*>(Out + (size_t)r0 * ostride + c) = v0;
      *reinterpret_cast<float2*>(Out + (size_t)(r0 + 8) * ostride + c) = v1;
    }
  }
}

// rna pre-round: out[i] = tf32(in[i]) (float4 vectorized)
__global__ void rna_kernel(const float* __restrict__ in, float* __restrict__ out,
                           int n4) {
  int i = blockIdx.x * blockDim.x + threadIdx.x;
  if (i < n4) {
    float4 v = reinterpret_cast<const float4*>(in)[i];
    v.x = to_tf32(v.x); v.y = to_tf32(v.y); v.z = to_tf32(v.z); v.w = to_tf32(v.w);
    reinterpret_cast<float4*>(out)[i] = v;
  }
}

// One CTA per batch; warp h = head h. Exact fp32 attention; rna'd output.
__global__ __launch_bounds__(256) void attn_kernel(const float* __restrict__ pb) {
  __shared__ float sX[Ss * 1536];
  __shared__ float sA[Hh][Ss][Ss];
  const int b = blockIdx.x;
  const int tid = threadIdx.x;
  const float* src = g_QKV + (size_t)b * (Ss * 1536);

  for (int i = tid; i < Ss * 1536 / 4; i += 256)
    reinterpret_cast<float4*>(sX)[i] = reinterpret_cast<const float4*>(src)[i];
  __syncthreads();

  const int h = tid >> 5, lane = tid & 31;
  const int c0 = h * HDd;

  if (lane < Ss * Ss) {
    int s = lane / Ss, tt = lane % Ss;
    float a = 0.f;
#pragma unroll
    for (int d = 0; d < HDd; d++)
      a += sX[s * 1536 + c0 + d] * sX[tt * 1536 + 512 + c0 + d];
    sA[h][s][tt] = a * 0.125f + pb[(h * Ss + s) * Ss + tt];
  }
  __syncwarp();

  if (lane < Ss) {
    float m = sA[h][lane][0];
#pragma unroll
    for (int tt = 1; tt < Ss; tt++) m = fmaxf(m, sA[h][lane][tt]);
    float e[Ss], sum = 0.f;
#pragma unroll
    for (int tt = 0; tt < Ss; tt++) {
      e[tt] = expf(sA[h][lane][tt] - m);
      sum += e[tt];
    }
    float inv = 1.0f / sum;
#pragma unroll
    for (int tt = 0; tt < Ss; tt++) sA[h][lane][tt] = e[tt] * inv;
  }
  __syncwarp();

  float* dst = g_O + (size_t)b * (Ss * Dd);
#pragma unroll
  for (int s = 0; s < Ss; s++) {
    float o0 = 0.f, o1 = 0.f;
#pragma unroll
    for (int tt = 0; tt < Ss; tt++) {
      float a = sA[h][s][tt];
      o0 += a * sX[tt * 1536 + 1024 + c0 + lane];
      o1 += a * sX[tt * 1536 + 1024 + c0 + lane + 32];
    }
    dst[s * Dd + c0 + lane] = to_tf32(o0);
    dst[s * Dd + c0 + lane + 32] = to_tf32(o1);
  }
}

extern "C" void kernel_launch(void* const* d_in, const int* in_sizes, int n_in,
                              void* d_out, int out_size) {
  (void)in_sizes; (void)n_in; (void)out_size;
  const float* x  = (const float*)d_in[0];
  const float* Wq = (const float*)d_in[1];
  const float* bq = (const float*)d_in[2];
  const float* Wk = (const float*)d_in[3];
  const float* bk = (const float*)d_in[4];
  const float* Wv = (const float*)d_in[5];
  const float* bv = (const float*)d_in[6];
  const float* Wo = (const float*)d_in[7];
  const float* bo = (const float*)d_in[8];
  const float* pb = (const float*)d_in[9];
  float* out = (float*)d_out;

  cudaFuncSetAttribute(gemm_tf32_kernel,
                       cudaFuncAttributeMaxDynamicSharedMemorySize, SMEM_BYTES);

  void *xp = nullptr, *qkv = nullptr, *op = nullptr, *wr = nullptr;
  cudaGetSymbolAddress(&xp, g_X);
  cudaGetSymbolAddress(&qkv, g_QKV);
  cudaGetSymbolAddress(&op, g_O);
  cudaGetSymbolAddress(&wr, g_Wr);
  float* Wr = (float*)wr;

  // 0) pre-round x and weights to tf32
  rna_kernel<<<(Mm * Dd / 4 + 255) / 256, 256>>>(x, (float*)xp, Mm * Dd / 4);
  rna_kernel<<<256, 256>>>(Wq, Wr + 0 * 262144, 65536);
  rna_kernel<<<256, 256>>>(Wk, Wr + 1 * 262144, 65536);
  rna_kernel<<<256, 256>>>(Wv, Wr + 2 * 262144, 65536);
  rna_kernel<<<256, 256>>>(Wo, Wr + 3 * 262144, 65536);

  // 1) fused QKV projection: [81920,512] x [512,1536] -> g_QKV [m][1536]
  gemm_tf32_kernel<<<dim3(1536 / BN, Mm / BM), 256, SMEM_BYTES>>>(
      (const float*)xp, Wr + 0 * 262144, Wr + 1 * 262144, Wr + 2 * 262144,
      bq, bk, bv, (float*)qkv, 1536);
  // 2) attention per batch
  attn_kernel<<<Bb, 256>>>(pb);
  // 3) output projection: [81920,512] x [512,512] -> d_out
  gemm_tf32_kernel<<<dim3(512 / BN, Mm / BM), 256, SMEM_BYTES>>>(
      (const float*)op, Wr + 3 * 262144, Wr + 3 * 262144, Wr + 3 * 262144,
      bo, bo, bo, out, 512);
}

// round 8
// speedup vs baseline: 1.1739x; 1.1080x over previous
#include <cuda_runtime.h>
#include <cstdint>

namespace {
constexpr int Bb = 16384, Ss = 5, Dd = 512, Hh = 8, HDd = 64;
constexpr int Mm = Bb * Ss;               // 81920
constexpr int BM = 128, BN = 128, BK = 32;
constexpr int KITERS = Dd / BK;           // 16
constexpr int SA_STRIDE = 36;             // conflict-free a-frag LDS (4g+t)
constexpr int SB_STRIDE = 136;            // conflict-free b-frag LDS (8t+g)
constexpr int A_STAGE = BM * SA_STRIDE;   // 4608 floats
constexpr int B_STAGE = BK * SB_STRIDE;   // 4352 floats
constexpr int STAGE_F = A_STAGE + B_STAGE;        // 8960 floats = 35840 B
constexpr int STAGES = 3;
constexpr int SMEM_BYTES = STAGES * STAGE_F * 4;  // 107520 B
}

// Scratch (device globals: allocation-free rule)
__device__ float g_X[(size_t)Mm * Dd];      // rna(x)
__device__ float g_QKV[(size_t)Mm * 1536];  // [m][ q | k | v ]
__device__ float g_O[(size_t)Mm * Dd];      // rna(attn out)
__device__ float g_Wr[4 * 512 * 512];       // rna(Wq|Wk|Wv|Wo), [k][n] layout

__device__ __forceinline__ float to_tf32(float x) {
  float y;
  asm("cvt.rna.tf32.f32 %0, %1;" : "=f"(y) : "f"(x));
  return y;
}

__device__ __forceinline__ void mma_tf32(float c[4], uint32_t a0, uint32_t a1,
                                         uint32_t a2, uint32_t a3,
                                         uint32_t b0, uint32_t b1) {
  asm volatile(
      "mma.sync.aligned.m16n8k8.row.col.f32.tf32.tf32.f32 "
      "{%0,%1,%2,%3}, {%4,%5,%6,%7}, {%8,%9}, {%0,%1,%2,%3};"
      : "+f"(c[0]), "+f"(c[1]), "+f"(c[2]), "+f"(c[3])
      : "r"(a0), "r"(a1), "r"(a2), "r"(a3), "r"(b0), "r"(b1));
}

__device__ __forceinline__ void cp_async16(void* smem_ptr, const void* gptr) {
  uint32_t saddr = (uint32_t)__cvta_generic_to_shared(smem_ptr);
  asm volatile("cp.async.cg.shared.global [%0], [%1], 16;" ::"r"(saddr),
               "l"(gptr));
}
__device__ __forceinline__ void cp_commit() {
  asm volatile("cp.async.commit_group;" ::);
}

// Out[:, col0:col0+128] = A[M,512] @ W_sec[512,512] + bias_sec
// A and W are PRE-ROUNDED to tf32 values (no in-loop cvt).
__global__ __launch_bounds__(256, 2) void gemm_tf32_kernel(
    const float* __restrict__ A, const float* __restrict__ W0,
    const float* __restrict__ W1, const float* __restrict__ W2,
    const float* __restrict__ bias0, const float* __restrict__ bias1,
    const float* __restrict__ bias2, float* __restrict__ Out, int ostride) {
  extern __shared__ float smem[];

  const int tid = threadIdx.x;
  const int m0 = blockIdx.y * BM;
  const int col0 = blockIdx.x * BN;
  const int sec = col0 >> 9;
  const int n0 = col0 & 511;
  const float* W = (sec == 0) ? W0 : ((sec == 1) ? W1 : W2);
  const float* bias = (sec == 0) ? bias0 : ((sec == 1) ? bias1 : bias2);

  const int warp = tid >> 5, lane = tid & 31;
  const int g = lane >> 2, t = lane & 3;
  const int warp_m = (warp >> 2) * 64;  // 2 warps in m
  const int warp_n = (warp & 3) * 32;   // 4 warps in n

  float acc[4][4][4];
#pragma unroll
  for (int i = 0; i < 4; i++)
#pragma unroll
    for (int j = 0; j < 4; j++)
#pragma unroll
      for (int r = 0; r < 4; r++) acc[i][j][r] = 0.f;

  auto issue_stage = [&](int it) {
    float* as = smem + (it % STAGES) * STAGE_F;
    float* bs = as + A_STAGE;
    const int k0 = it * BK;
    // A tile: 128 rows x 32 floats = 1024 16B chunks (4/thread)
#pragma unroll
    for (int i = 0; i < 4; i++) {
      int cid = tid + i * 256;
      int row = cid >> 3, q = cid & 7;
      cp_async16(as + row * SA_STRIDE + q * 4,
                 A + (size_t)(m0 + row) * Dd + k0 + q * 4);
    }
    // B tile: 32 rows x 128 floats = 1024 16B chunks (4/thread)
#pragma unroll
    for (int i = 0; i < 4; i++) {
      int cid = tid + i * 256;
      int row = cid >> 5, q = cid & 31;
      cp_async16(bs + row * SB_STRIDE + q * 4,
                 W + (size_t)(k0 + row) * Dd + n0 + q * 4);
    }
    cp_commit();
  };

  issue_stage(0);
  issue_stage(1);

  for (int it = 0; it < KITERS; it++) {
    if (it < KITERS - 1)
      asm volatile("cp.async.wait_group 1;" ::: "memory");
    else
      asm volatile("cp.async.wait_group 0;" ::: "memory");
    __syncthreads();
    // issue(it+2) overwrites buffer (it+2)%3 == (it-1)%3: compute(it-1) is
    // retired by the barrier above, and compute(it) uses buffer it%3. Safe.
    if (it + 2 < KITERS) issue_stage(it + 2);

    const float* as = smem + (it % STAGES) * STAGE_F;
    const float* bs = as + A_STAGE;
#pragma unroll
    for (int ks = 0; ks < BK; ks += 8) {
      uint32_t af[4][4], bf[4][2];
#pragma unroll
      for (int mi = 0; mi < 4; mi++) {
        const float* ap = as + (warp_m + mi * 16 + g) * SA_STRIDE + ks + t;
        af[mi][0] = __float_as_uint(ap[0]);
        af[mi][1] = __float_as_uint(ap[8 * SA_STRIDE]);
        af[mi][2] = __float_as_uint(ap[4]);
        af[mi][3] = __float_as_uint(ap[8 * SA_STRIDE + 4]);
      }
#pragma unroll
      for (int ni = 0; ni < 4; ni++) {
        const float* bp = bs + (ks + t) * SB_STRIDE + warp_n + ni * 8 + g;
        bf[ni][0] = __float_as_uint(bp[0]);
        bf[ni][1] = __float_as_uint(bp[4 * SB_STRIDE]);
      }
#pragma unroll
      for (int mi = 0; mi < 4; mi++)
#pragma unroll
        for (int ni = 0; ni < 4; ni++)
          mma_tf32(acc[mi][ni], af[mi][0], af[mi][1], af[mi][2], af[mi][3],
                   bf[ni][0], bf[ni][1]);
    }
    __syncthreads();
  }

  // epilogue: bias + store
#pragma unroll
  for (int mi = 0; mi < 4; mi++) {
    int r0 = m0 + warp_m + mi * 16 + g;
#pragma unroll
    for (int ni = 0; ni < 4; ni++) {
      int c = col0 + warp_n + ni * 8 + 2 * t;
      float b0v = bias[c & 511], b1v = bias[(c & 511) + 1];
      float2 v0 = make_float2(acc[mi][ni][0] + b0v, acc[mi][ni][1] + b1v);
      float2 v1 = make_float2(acc[mi][ni][2] + b0v, acc[mi][ni][3] + b1v);
      *reinterpret_cast<float2*>(Out + (size_t)r0 * ostride + c) = v0;
      *reinterpret_cast<float2*>(Out + (size_t)(r0 + 8) * ostride + c) = v1;
    }
  }
}

// rna pre-round: out[i] = tf32(in[i]) (float4 vectorized)
__global__ void rna_kernel(const float* __restrict__ in, float* __restrict__ out,
                           int n4) {
  int i = blockIdx.x * blockDim.x + threadIdx.x;
  if (i < n4) {
    float4 v = reinterpret_cast<const float4*>(in)[i];
    v.x = to_tf32(v.x); v.y = to_tf32(v.y); v.z = to_tf32(v.z); v.w = to_tf32(v.w);
    reinterpret_cast<float4*>(out)[i] = v;
  }
}

// One CTA per batch; warp h = head h. Exact fp32 attention; rna'd output.
__global__ __launch_bounds__(256) void attn_kernel(const float* __restrict__ pb) {
  __shared__ float sX[Ss * 1536];
  __shared__ float sA[Hh][Ss][Ss];
  const int b = blockIdx.x;
  const int tid = threadIdx.x;
  const float* src = g_QKV + (size_t)b * (Ss * 1536);

  for (int i = tid; i < Ss * 1536 / 4; i += 256)
    reinterpret_cast<float4*>(sX)[i] = reinterpret_cast<const float4*>(src)[i];
  __syncthreads();

  const int h = tid >> 5, lane = tid & 31;
  const int c0 = h * HDd;

  if (lane < Ss * Ss) {
    int s = lane / Ss, tt = lane % Ss;
    float a = 0.f;
#pragma unroll
    for (int d = 0; d < HDd; d++)
      a += sX[s * 1536 + c0 + d] * sX[tt * 1536 + 512 + c0 + d];
    sA[h][s][tt] = a * 0.125f + pb[(h * Ss + s) * Ss + tt];
  }
  __syncwarp();

  if (lane < Ss) {
    float m = sA[h][lane][0];
#pragma unroll
    for (int tt = 1; tt < Ss; tt++) m = fmaxf(m, sA[h][lane][tt]);
    float e[Ss], sum = 0.f;
#pragma unroll
    for (int tt = 0; tt < Ss; tt++) {
      e[tt] = expf(sA[h][lane][tt] - m);
      sum += e[tt];
    }
    float inv = 1.0f / sum;
#pragma unroll
    for (int tt = 0; tt < Ss; tt++) sA[h][lane][tt] = e[tt] * inv;
  }
  __syncwarp();

  float* dst = g_O + (size_t)b * (Ss * Dd);
#pragma unroll
  for (int s = 0; s < Ss; s++) {
    float o0 = 0.f, o1 = 0.f;
#pragma unroll
    for (int tt = 0; tt < Ss; tt++) {
      float a = sA[h][s][tt];
      o0 += a * sX[tt * 1536 + 1024 + c0 + lane];
      o1 += a * sX[tt * 1536 + 1024 + c0 + lane + 32];
    }
    dst[s * Dd + c0 + lane] = to_tf32(o0);
    dst[s * Dd + c0 + lane + 32] = to_tf32(o1);
  }
}

extern "C" void kernel_launch(void* const* d_in, const int* in_sizes, int n_in,
                              void* d_out, int out_size) {
  (void)in_sizes; (void)n_in; (void)out_size;
  const float* x  = (const float*)d_in[0];
  const float* Wq = (const float*)d_in[1];
  const float* bq = (const float*)d_in[2];
  const float* Wk = (const float*)d_in[3];
  const float* bk = (const float*)d_in[4];
  const float* Wv = (const float*)d_in[5];
  const float* bv = (const float*)d_in[6];
  const float* Wo = (const float*)d_in[7];
  const float* bo = (const float*)d_in[8];
  const float* pb = (const float*)d_in[9];
  float* out = (float*)d_out;

  cudaFuncSetAttribute(gemm_tf32_kernel,
                       cudaFuncAttributeMaxDynamicSharedMemorySize, SMEM_BYTES);

  void *xp = nullptr, *qkv = nullptr, *op = nullptr, *wr = nullptr;
  cudaGetSymbolAddress(&xp, g_X);
  cudaGetSymbolAddress(&qkv, g_QKV);
  cudaGetSymbolAddress(&op, g_O);
  cudaGetSymbolAddress(&wr, g_Wr);
  float* Wr = (float*)wr;

  // 0) pre-round x and weights to tf32
  rna_kernel<<<(Mm * Dd / 4 + 255) / 256, 256>>>(x, (float*)xp, Mm * Dd / 4);
  rna_kernel<<<256, 256>>>(Wq, Wr + 0 * 262144, 65536);
  rna_kernel<<<256, 256>>>(Wk, Wr + 1 * 262144, 65536);
  rna_kernel<<<256, 256>>>(Wv, Wr + 2 * 262144, 65536);
  rna_kernel<<<256, 256>>>(Wo, Wr + 3 * 262144, 65536);

  // 1) fused QKV projection: [81920,512] x [512,1536] -> g_QKV [m][1536]
  gemm_tf32_kernel<<<dim3(1536 / BN, Mm / BM), 256, SMEM_BYTES>>>(
      (const float*)xp, Wr + 0 * 262144, Wr + 1 * 262144, Wr + 2 * 262144,
      bq, bk, bv, (float*)qkv, 1536);
  // 2) attention per batch
  attn_kernel<<<Bb, 256>>>(pb);
  // 3) output projection: [81920,512] x [512,512] -> d_out
  gemm_tf32_kernel<<<dim3(512 / BN, Mm / BM), 256, SMEM_BYTES>>>(
      (const float*)op, Wr + 3 * 262144, Wr + 3 * 262144, Wr + 3 * 262144,
      bo, bo, bo, out, 512);
}

// round 9
// speedup vs baseline: 1.1806x; 1.0057x over previous
#include <cuda_runtime.h>
#include <cstdint>

namespace {
constexpr int Bb = 16384, Ss = 5, Dd = 512, Hh = 8, HDd = 64;
constexpr int Mm = Bb * Ss;               // 81920
constexpr int BM = 128, BN = 128, BK = 32;
constexpr int KITERS = Dd / BK;           // 16
constexpr int SA_STRIDE = 36;             // conflict-free a-frag LDS (4g+t)
constexpr int SB_STRIDE = 136;            // conflict-free b-frag LDS (8t+g)
constexpr int A_STAGE = BM * SA_STRIDE;   // 4608 floats
constexpr int B_STAGE = BK * SB_STRIDE;   // 4352 floats
constexpr int STAGE_F = A_STAGE + B_STAGE;        // 8960 floats = 35840 B
constexpr int STAGES = 3;
constexpr int SMEM_BYTES = STAGES * STAGE_F * 4;  // 107520 B
}

// Scratch (device globals: allocation-free rule)
__device__ float g_QKV[(size_t)Mm * 1536];  // [m][ q | k | v ]
__device__ float g_O[(size_t)Mm * Dd];      // rna(attn out)
__device__ float g_Wr[4 * 512 * 512];       // rna(Wq|Wk|Wv|Wo), [k][n] layout

__device__ __forceinline__ float to_tf32(float x) {
  float y;
  asm("cvt.rna.tf32.f32 %0, %1;" : "=f"(y) : "f"(x));
  return y;
}

__device__ __forceinline__ void mma_tf32(float c[4], uint32_t a0, uint32_t a1,
                                         uint32_t a2, uint32_t a3,
                                         uint32_t b0, uint32_t b1) {
  asm volatile(
      "mma.sync.aligned.m16n8k8.row.col.f32.tf32.tf32.f32 "
      "{%0,%1,%2,%3}, {%4,%5,%6,%7}, {%8,%9}, {%0,%1,%2,%3};"
      : "+f"(c[0]), "+f"(c[1]), "+f"(c[2]), "+f"(c[3])
      : "r"(a0), "r"(a1), "r"(a2), "r"(a3), "r"(b0), "r"(b1));
}

__device__ __forceinline__ void cp_async16(void* smem_ptr, const void* gptr) {
  uint32_t saddr = (uint32_t)__cvta_generic_to_shared(smem_ptr);
  asm volatile("cp.async.cg.shared.global [%0], [%1], 16;" ::"r"(saddr),
               "l"(gptr));
}
__device__ __forceinline__ void cp_commit() {
  asm volatile("cp.async.commit_group;" ::);
}

// Out[:, col0:col0+128] = rna(A[M,512]) @ W_sec[512,512] + bias_sec
// W is PRE-ROUNDED tf32; A is rounded per-fragment in the MMA loop (rna).
__global__ __launch_bounds__(256, 2) void gemm_tf32_kernel(
    const float* __restrict__ A, const float* __restrict__ W0,
    const float* __restrict__ W1, const float* __restrict__ W2,
    const float* __restrict__ bias0, const float* __restrict__ bias1,
    const float* __restrict__ bias2, float* __restrict__ Out, int ostride) {
  extern __shared__ float smem[];

  const int tid = threadIdx.x;
  const int m0 = blockIdx.y * BM;
  const int col0 = blockIdx.x * BN;
  const int sec = col0 >> 9;
  const int n0 = col0 & 511;
  const float* W = (sec == 0) ? W0 : ((sec == 1) ? W1 : W2);
  const float* bias = (sec == 0) ? bias0 : ((sec == 1) ? bias1 : bias2);

  const int warp = tid >> 5, lane = tid & 31;
  const int g = lane >> 2, t = lane & 3;
  const int warp_m = (warp >> 2) * 64;  // 2 warps in m
  const int warp_n = (warp & 3) * 32;   // 4 warps in n

  float acc[4][4][4];
#pragma unroll
  for (int i = 0; i < 4; i++)
#pragma unroll
    for (int j = 0; j < 4; j++)
#pragma unroll
      for (int r = 0; r < 4; r++) acc[i][j][r] = 0.f;

  auto issue_stage = [&](int it) {
    float* as = smem + (it % STAGES) * STAGE_F;
    float* bs = as + A_STAGE;
    const int k0 = it * BK;
    // A tile: 128 rows x 32 floats = 1024 16B chunks (4/thread)
#pragma unroll
    for (int i = 0; i < 4; i++) {
      int cid = tid + i * 256;
      int row = cid >> 3, q = cid & 7;
      cp_async16(as + row * SA_STRIDE + q * 4,
                 A + (size_t)(m0 + row) * Dd + k0 + q * 4);
    }
    // B tile: 32 rows x 128 floats = 1024 16B chunks (4/thread)
#pragma unroll
    for (int i = 0; i < 4; i++) {
      int cid = tid + i * 256;
      int row = cid >> 5, q = cid & 31;
      cp_async16(bs + row * SB_STRIDE + q * 4,
                 W + (size_t)(k0 + row) * Dd + n0 + q * 4);
    }
    cp_commit();
  };

  issue_stage(0);
  issue_stage(1);

  for (int it = 0; it < KITERS; it++) {
    if (it < KITERS - 1)
      asm volatile("cp.async.wait_group 1;" ::: "memory");
    else
      asm volatile("cp.async.wait_group 0;" ::: "memory");
    __syncthreads();  // single barrier per iter: all warps retired compute(it-1)
    // issue(it+2) overwrites buffer (it+2)%3 == (it-1)%3 -> safe after barrier.
    if (it + 2 < KITERS) issue_stage(it + 2);

    const float* as = smem + (it % STAGES) * STAGE_F;
    const float* bs = as + A_STAGE;
#pragma unroll
    for (int ks = 0; ks < BK; ks += 8) {
      uint32_t af[4][4], bf[4][2];
#pragma unroll
      for (int mi = 0; mi < 4; mi++) {
        const float* ap = as + (warp_m + mi * 16 + g) * SA_STRIDE + ks + t;
        af[mi][0] = __float_as_uint(to_tf32(ap[0]));
        af[mi][1] = __float_as_uint(to_tf32(ap[8 * SA_STRIDE]));
        af[mi][2] = __float_as_uint(to_tf32(ap[4]));
        af[mi][3] = __float_as_uint(to_tf32(ap[8 * SA_STRIDE + 4]));
      }
#pragma unroll
      for (int ni = 0; ni < 4; ni++) {
        const float* bp = bs + (ks + t) * SB_STRIDE + warp_n + ni * 8 + g;
        bf[ni][0] = __float_as_uint(bp[0]);
        bf[ni][1] = __float_as_uint(bp[4 * SB_STRIDE]);
      }
#pragma unroll
      for (int mi = 0; mi < 4; mi++)
#pragma unroll
        for (int ni = 0; ni < 4; ni++)
          mma_tf32(acc[mi][ni], af[mi][0], af[mi][1], af[mi][2], af[mi][3],
                   bf[ni][0], bf[ni][1]);
    }
    // no loop-end barrier needed (see comment above)
  }

  // epilogue: bias + store
#pragma unroll
  for (int mi = 0; mi < 4; mi++) {
    int r0 = m0 + warp_m + mi * 16 + g;
#pragma unroll
    for (int ni = 0; ni < 4; ni++) {
      int c = col0 + warp_n + ni * 8 + 2 * t;
      float b0v = bias[c & 511], b1v = bias[(c & 511) + 1];
      float2 v0 = make_float2(acc[mi][ni][0] + b0v, acc[mi][ni][1] + b1v);
      float2 v1 = make_float2(acc[mi][ni][2] + b0v, acc[mi][ni][3] + b1v);
      *reinterpret_cast<float2*>(Out + (size_t)r0 * ostride + c) = v0;
      *reinterpret_cast<float2*>(Out + (size_t)(r0 + 8) * ostride + c) = v1;
    }
  }
}

// Fused weight pre-round: one launch, blockIdx.y picks the weight matrix.
__global__ void rna_w_kernel(const float* __restrict__ Wq,
                             const float* __restrict__ Wk,
                             const float* __restrict__ Wv,
                             const float* __restrict__ Wo) {
  const int w = blockIdx.y;
  const float* src = (w == 0) ? Wq : (w == 1) ? Wk : (w == 2) ? Wv : Wo;
  float* dst = g_Wr + (size_t)w * 262144;
  int i = blockIdx.x * blockDim.x + threadIdx.x;  // 65536 float4 per matrix
  float4 v = reinterpret_cast<const float4*>(src)[i];
  v.x = to_tf32(v.x); v.y = to_tf32(v.y); v.z = to_tf32(v.z); v.w = to_tf32(v.w);
  reinterpret_cast<float4*>(dst)[i] = v;
}

// One CTA per batch; warp h = head h. Exact fp32 attention; rna'd output.
__global__ __launch_bounds__(256) void attn_kernel(const float* __restrict__ pb) {
  __shared__ float sX[Ss * 1536];
  __shared__ float sA[Hh][Ss][Ss];
  const int b = blockIdx.x;
  const int tid = threadIdx.x;
  const float* src = g_QKV + (size_t)b * (Ss * 1536);

  for (int i = tid; i < Ss * 1536 / 4; i += 256)
    reinterpret_cast<float4*>(sX)[i] = reinterpret_cast<const float4*>(src)[i];
  __syncthreads();

  const int h = tid >> 5, lane = tid & 31;
  const int c0 = h * HDd;

  if (lane < Ss * Ss) {
    int s = lane / Ss, tt = lane % Ss;
    float a = 0.f;
#pragma unroll
    for (int d = 0; d < HDd; d++)
      a += sX[s * 1536 + c0 + d] * sX[tt * 1536 + 512 + c0 + d];
    sA[h][s][tt] = a * 0.125f + pb[(h * Ss + s) * Ss + tt];
  }
  __syncwarp();

  if (lane < Ss) {
    float m = sA[h][lane][0];
#pragma unroll
    for (int tt = 1; tt < Ss; tt++) m = fmaxf(m, sA[h][lane][tt]);
    float e[Ss], sum = 0.f;
#pragma unroll
    for (int tt = 0; tt < Ss; tt++) {
      e[tt] = expf(sA[h][lane][tt] - m);
      sum += e[tt];
    }
    float inv = 1.0f / sum;
#pragma unroll
    for (int tt = 0; tt < Ss; tt++) sA[h][lane][tt] = e[tt] * inv;
  }
  __syncwarp();

  float* dst = g_O + (size_t)b * (Ss * Dd);
#pragma unroll
  for (int s = 0; s < Ss; s++) {
    float o0 = 0.f, o1 = 0.f;
#pragma unroll
    for (int tt = 0; tt < Ss; tt++) {
      float a = sA[h][s][tt];
      o0 += a * sX[tt * 1536 + 1024 + c0 + lane];
      o1 += a * sX[tt * 1536 + 1024 + c0 + lane + 32];
    }
    dst[s * Dd + c0 + lane] = to_tf32(o0);
    dst[s * Dd + c0 + lane + 32] = to_tf32(o1);
  }
}

extern "C" void kernel_launch(void* const* d_in, const int* in_sizes, int n_in,
                              void* d_out, int out_size) {
  (void)in_sizes; (void)n_in; (void)out_size;
  const float* x  = (const float*)d_in[0];
  const float* Wq = (const float*)d_in[1];
  const float* bq = (const float*)d_in[2];
  const float* Wk = (const float*)d_in[3];
  const float* bk = (const float*)d_in[4];
  const float* Wv = (const float*)d_in[5];
  const float* bv = (const float*)d_in[6];
  const float* Wo = (const float*)d_in[7];
  const float* bo = (const float*)d_in[8];
  const float* pb = (const float*)d_in[9];
  float* out = (float*)d_out;

  cudaFuncSetAttribute(gemm_tf32_kernel,
                       cudaFuncAttributeMaxDynamicSharedMemorySize, SMEM_BYTES);

  void *qkv = nullptr, *op = nullptr, *wr = nullptr;
  cudaGetSymbolAddress(&qkv, g_QKV);
  cudaGetSymbolAddress(&op, g_O);
  cudaGetSymbolAddress(&wr, g_Wr);
  float* Wr = (float*)wr;

  // 0) pre-round weights to tf32 (single launch)
  rna_w_kernel<<<dim3(256, 4), 256>>>(Wq, Wk, Wv, Wo);

  // 1) fused QKV projection: rna(x) @ [Wq|Wk|Wv] -> g_QKV [m][1536]
  gemm_tf32_kernel<<<dim3(1536 / BN, Mm / BM), 256, SMEM_BYTES>>>(
      x, Wr + 0 * 262144, Wr + 1 * 262144, Wr + 2 * 262144,
      bq, bk, bv, (float*)qkv, 1536);
  // 2) attention per batch
  attn_kernel<<<Bb, 256>>>(pb);
  // 3) output projection: g_O @ Wo -> d_out
  gemm_tf32_kernel<<<dim3(512 / BN, Mm / BM), 256, SMEM_BYTES>>>(
      (const float*)op, Wr + 3 * 262144, Wr + 3 * 262144, Wr + 3 * 262144,
      bo, bo, bo, out, 512);
}

// round 10
// speedup vs baseline: 1.2419x; 1.0519x over previous
#include <cuda_runtime.h>
#include <cstdint>

namespace {
constexpr int Bb = 16384, Ss = 5, Dd = 512, Hh = 8, HDd = 64;
constexpr int Mm = Bb * Ss;               // 81920
constexpr int BM = 128, BN = 128, BK = 32;
constexpr int KITERS = Dd / BK;           // 16
constexpr int SA_STRIDE = 36;             // 144B rows: ldmatrix phases conflict-free
constexpr int SB_STRIDE = 136;            // conflict-free b-frag LDS (8t+g)
constexpr int A_STAGE = BM * SA_STRIDE;   // 4608 floats
constexpr int B_STAGE = BK * SB_STRIDE;   // 4352 floats
constexpr int STAGE_F = A_STAGE + B_STAGE;        // 8960 floats = 35840 B
constexpr int STAGES = 3;
constexpr int SMEM_BYTES = STAGES * STAGE_F * 4;  // 107520 B
}

// Scratch (device globals: allocation-free rule)
__device__ float g_QKV[(size_t)Mm * 1536];  // [m][ q | k | v ]
__device__ float g_O[(size_t)Mm * Dd];      // rna(attn out)
__device__ float g_Wr[4 * 512 * 512];       // rna(Wq|Wk|Wv|Wo), [k][n] layout

__device__ __forceinline__ float to_tf32(float x) {
  float y;
  asm("cvt.rna.tf32.f32 %0, %1;" : "=f"(y) : "f"(x));
  return y;
}
__device__ __forceinline__ uint32_t cvt_u(uint32_t x) {
  return __float_as_uint(to_tf32(__uint_as_float(x)));
}

__device__ __forceinline__ void mma_tf32(float c[4], uint32_t a0, uint32_t a1,
                                         uint32_t a2, uint32_t a3,
                                         uint32_t b0, uint32_t b1) {
  asm volatile(
      "mma.sync.aligned.m16n8k8.row.col.f32.tf32.tf32.f32 "
      "{%0,%1,%2,%3}, {%4,%5,%6,%7}, {%8,%9}, {%0,%1,%2,%3};"
      : "+f"(c[0]), "+f"(c[1]), "+f"(c[2]), "+f"(c[3])
      : "r"(a0), "r"(a1), "r"(a2), "r"(a3), "r"(b0), "r"(b1));
}

__device__ __forceinline__ void ldmatrix_x4(uint32_t r[4], uint32_t addr) {
  asm volatile(
      "ldmatrix.sync.aligned.m8n8.x4.shared.b16 {%0,%1,%2,%3}, [%4];"
      : "=r"(r[0]), "=r"(r[1]), "=r"(r[2]), "=r"(r[3])
      : "r"(addr));
}

__device__ __forceinline__ void cp_async16(void* smem_ptr, const void* gptr) {
  uint32_t saddr = (uint32_t)__cvta_generic_to_shared(smem_ptr);
  asm volatile("cp.async.cg.shared.global [%0], [%1], 16;" ::"r"(saddr),
               "l"(gptr));
}
__device__ __forceinline__ void cp_commit() {
  asm volatile("cp.async.commit_group;" ::);
}

// Out[:, col0:col0+128] = A[M,512] @ W_sec[512,512] + bias_sec
// W is PRE-ROUNDED tf32. A: if CVT_A, rna per fragment; else HW RZ-truncation.
template <bool CVT_A>
__global__ __launch_bounds__(256, 2) void gemm_tf32_kernel(
    const float* __restrict__ A, const float* __restrict__ W0,
    const float* __restrict__ W1, const float* __restrict__ W2,
    const float* __restrict__ bias0, const float* __restrict__ bias1,
    const float* __restrict__ bias2, float* __restrict__ Out, int ostride) {
  extern __shared__ float smem[];
  const uint32_t sb = (uint32_t)__cvta_generic_to_shared(smem);

  const int tid = threadIdx.x;
  const int m0 = blockIdx.y * BM;
  const int col0 = blockIdx.x * BN;
  const int sec = col0 >> 9;
  const int n0 = col0 & 511;
  const float* W = (sec == 0) ? W0 : ((sec == 1) ? W1 : W2);
  const float* bias = (sec == 0) ? bias0 : ((sec == 1) ? bias1 : bias2);

  const int warp = tid >> 5, lane = tid & 31;
  const int g = lane >> 2, t = lane & 3;
  const int warp_m = (warp >> 2) * 64;  // 2 warps in m
  const int warp_n = (warp & 3) * 32;   // 4 warps in n

  // ldmatrix per-lane source row/byte: lanes 0-7 -> rows 0-7 (c0-3),
  // 8-15 -> rows 8-15 (c0-3), 16-23 -> rows 0-7 (c4-7), 24-31 -> rows 8-15 (c4-7)
  const int a_lm_row = warp_m + (lane & 7) + ((lane >> 3) & 1) * 8;
  const uint32_t a_lm_byte = ((lane >> 4) & 1) * 16;

  float acc[4][4][4];
#pragma unroll
  for (int i = 0; i < 4; i++)
#pragma unroll
    for (int j = 0; j < 4; j++)
#pragma unroll
      for (int r = 0; r < 4; r++) acc[i][j][r] = 0.f;

  auto issue_stage = [&](int it) {
    float* as = smem + (it % STAGES) * STAGE_F;
    float* bs = as + A_STAGE;
    const int k0 = it * BK;
#pragma unroll
    for (int i = 0; i < 4; i++) {
      int cid = tid + i * 256;
      int row = cid >> 3, q = cid & 7;
      cp_async16(as + row * SA_STRIDE + q * 4,
                 A + (size_t)(m0 + row) * Dd + k0 + q * 4);
    }
#pragma unroll
    for (int i = 0; i < 4; i++) {
      int cid = tid + i * 256;
      int row = cid >> 5, q = cid & 31;
      cp_async16(bs + row * SB_STRIDE + q * 4,
                 W + (size_t)(k0 + row) * Dd + n0 + q * 4);
    }
    cp_commit();
  };

  issue_stage(0);
  issue_stage(1);

  for (int it = 0; it < KITERS; it++) {
    if (it < KITERS - 1)
      asm volatile("cp.async.wait_group 1;" ::: "memory");
    else
      asm volatile("cp.async.wait_group 0;" ::: "memory");
    __syncthreads();  // single barrier per iter
    if (it + 2 < KITERS) issue_stage(it + 2);

    const uint32_t a_base = sb + (uint32_t)((it % STAGES) * STAGE_F * 4) +
                            (uint32_t)(a_lm_row * (SA_STRIDE * 4)) + a_lm_byte;
    const float* bs = smem + (it % STAGES) * STAGE_F + A_STAGE;
#pragma unroll
    for (int ks = 0; ks < BK; ks += 8) {
      uint32_t af[4][4], bf[4][2];
#pragma unroll
      for (int mi = 0; mi < 4; mi++) {
        ldmatrix_x4(af[mi], a_base + mi * (16 * SA_STRIDE * 4) + ks * 4);
        if (CVT_A) {
#pragma unroll
          for (int r = 0; r < 4; r++) af[mi][r] = cvt_u(af[mi][r]);
        }
      }
#pragma unroll
      for (int ni = 0; ni < 4; ni++) {
        const float* bp = bs + (ks + t) * SB_STRIDE + warp_n + ni * 8 + g;
        bf[ni][0] = __float_as_uint(bp[0]);
        bf[ni][1] = __float_as_uint(bp[4 * SB_STRIDE]);
      }
#pragma unroll
      for (int mi = 0; mi < 4; mi++)
#pragma unroll
        for (int ni = 0; ni < 4; ni++)
          mma_tf32(acc[mi][ni], af[mi][0], af[mi][1], af[mi][2], af[mi][3],
                   bf[ni][0], bf[ni][1]);
    }
  }

  // epilogue: bias + store
#pragma unroll
  for (int mi = 0; mi < 4; mi++) {
    int r0 = m0 + warp_m + mi * 16 + g;
#pragma unroll
    for (int ni = 0; ni < 4; ni++) {
      int c = col0 + warp_n + ni * 8 + 2 * t;
      float b0v = bias[c & 511], b1v = bias[(c & 511) + 1];
      float2 v0 = make_float2(acc[mi][ni][0] + b0v, acc[mi][ni][1] + b1v);
      float2 v1 = make_float2(acc[mi][ni][2] + b0v, acc[mi][ni][3] + b1v);
      *reinterpret_cast<float2*>(Out + (size_t)r0 * ostride + c) = v0;
      *reinterpret_cast<float2*>(Out + (size_t)(r0 + 8) * ostride + c) = v1;
    }
  }
}

// Fused weight pre-round: one launch, blockIdx.y picks the weight matrix.
__global__ void rna_w_kernel(const float* __restrict__ Wq,
                             const float* __restrict__ Wk,
                             const float* __restrict__ Wv,
                             const float* __restrict__ Wo) {
  const int w = blockIdx.y;
  const float* src = (w == 0) ? Wq : (w == 1) ? Wk : (w == 2) ? Wv : Wo;
  float* dst = g_Wr + (size_t)w * 262144;
  int i = blockIdx.x * blockDim.x + threadIdx.x;
  float4 v = reinterpret_cast<const float4*>(src)[i];
  v.x = to_tf32(v.x); v.y = to_tf32(v.y); v.z = to_tf32(v.z); v.w = to_tf32(v.w);
  reinterpret_cast<float4*>(dst)[i] = v;
}

// 512 threads, 2 batches per CTA; warp (h within half) = head h.
__global__ __launch_bounds__(512) void attn_kernel(const float* __restrict__ pb) {
  __shared__ float sX[2][Ss * 1536];
  __shared__ float sA[2][Hh][Ss][Ss];
  const int b2 = blockIdx.x;  // pair of batches
  const int tid = threadIdx.x;
  const float* src = g_QKV + (size_t)b2 * (2 * Ss * 1536);

  for (int i = tid; i < 2 * Ss * 1536 / 4; i += 512)
    reinterpret_cast<float4*>(&sX[0][0])[i] =
        reinterpret_cast<const float4*>(src)[i];
  __syncthreads();

  const int half = tid >> 8;            // which batch of the pair
  const int h = (tid >> 5) & 7, lane = tid & 31;
  const int c0 = h * HDd;
  const float* X = sX[half];
  float (*Arow)[Ss] = sA[half][h];

  if (lane < Ss * Ss) {
    int s = lane / Ss, tt = lane % Ss;
    float a = 0.f;
#pragma unroll
    for (int d = 0; d < HDd; d++)
      a += X[s * 1536 + c0 + d] * X[tt * 1536 + 512 + c0 + d];
    Arow[s][tt] = a * 0.125f + pb[(h * Ss + s) * Ss + tt];
  }
  __syncwarp();

  if (lane < Ss) {
    float m = Arow[lane][0];
#pragma unroll
    for (int tt = 1; tt < Ss; tt++) m = fmaxf(m, Arow[lane][tt]);
    float e[Ss], sum = 0.f;
#pragma unroll
    for (int tt = 0; tt < Ss; tt++) {
      e[tt] = expf(Arow[lane][tt] - m);
      sum += e[tt];
    }
    float inv = 1.0f / sum;
#pragma unroll
    for (int tt = 0; tt < Ss; tt++) Arow[lane][tt] = e[tt] * inv;
  }
  __syncwarp();

  float* dst = g_O + ((size_t)b2 * 2 + half) * (Ss * Dd);
#pragma unroll
  for (int s = 0; s < Ss; s++) {
    float o0 = 0.f, o1 = 0.f;
#pragma unroll
    for (int tt = 0; tt < Ss; tt++) {
      float a = Arow[s][tt];
      o0 += a * X[tt * 1536 + 1024 + c0 + lane];
      o1 += a * X[tt * 1536 + 1024 + c0 + lane + 32];
    }
    dst[s * Dd + c0 + lane] = to_tf32(o0);
    dst[s * Dd + c0 + lane + 32] = to_tf32(o1);
  }
}

extern "C" void kernel_launch(void* const* d_in, const int* in_sizes, int n_in,
                              void* d_out, int out_size) {
  (void)in_sizes; (void)n_in; (void)out_size;
  const float* x  = (const float*)d_in[0];
  const float* Wq = (const float*)d_in[1];
  const float* bq = (const float*)d_in[2];
  const float* Wk = (const float*)d_in[3];
  const float* bk = (const float*)d_in[4];
  const float* Wv = (const float*)d_in[5];
  const float* bv = (const float*)d_in[6];
  const float* Wo = (const float*)d_in[7];
  const float* bo = (const float*)d_in[8];
  const float* pb = (const float*)d_in[9];
  float* out = (float*)d_out;

  cudaFuncSetAttribute(gemm_tf32_kernel<false>,
                       cudaFuncAttributeMaxDynamicSharedMemorySize, SMEM_BYTES);

  void *qkv = nullptr, *op = nullptr, *wr = nullptr;
  cudaGetSymbolAddress(&qkv, g_QKV);
  cudaGetSymbolAddress(&op, g_O);
  cudaGetSymbolAddress(&wr, g_Wr);
  float* Wr = (float*)wr;

  // 0) pre-round weights to tf32 (single launch)
  rna_w_kernel<<<dim3(256, 4), 256>>>(Wq, Wk, Wv, Wo);

  // 1) fused QKV projection: x @ [Wq|Wk|Wv] -> g_QKV [m][1536] (A RZ-trunc)
  gemm_tf32_kernel<false><<<dim3(1536 / BN, Mm / BM), 256, SMEM_BYTES>>>(
      x, Wr + 0 * 262144, Wr + 1 * 262144, Wr + 2 * 262144,
      bq, bk, bv, (float*)qkv, 1536);
  // 2) attention, 2 batches per CTA
  attn_kernel<<<Bb / 2, 512>>>(pb);
  // 3) output projection: g_O (pre-rna'd) @ Wo -> d_out
  gemm_tf32_kernel<false><<<dim3(512 / BN, Mm / BM), 256, SMEM_BYTES>>>(
      (const float*)op, Wr + 3 * 262144, Wr + 3 * 262144, Wr + 3 * 262144,
      bo, bo, bo, out, 512);
}